// round 1
// baseline (speedup 1.0000x reference)
#include <cuda_runtime.h>
#include <cuda_bf16.h>
#include <cstdint>
#include <cstdio>

// ---------------- problem constants ----------------
#define B_  2
#define L_  1024
#define D_  1024
#define NL_ 4
#define V_  50280
#define DI_ 2048           // 2*D
#define DS_ 16
#define DC_ 4
#define DTR_ 64            // D/16
#define EPS_ 1e-5f
#define ML_ (B_*L_)        // 2048 rows in all GEMMs

// ---------------- scratch (device global, no allocs) ----------------
// offsets in floats
#define OFF_HIDDEN   0
#define OFF_RESID    (OFF_HIDDEN + ML_*D_)        // 2,097,152
#define OFF_HNORM    (OFF_RESID  + ML_*D_)
#define OFF_XZ       (OFF_HNORM  + ML_*D_)        // [2048, 4096]
#define OFF_XCONV    (OFF_XZ     + ML_*2*DI_)     // [2048, 2048]
#define OFF_DBL      (OFF_XCONV  + ML_*DI_)       // [2048, 96]
#define OFF_DT       (OFF_DBL    + ML_*96)        // [2048, 2048]
#define OFF_Y        (OFF_DT     + ML_*DI_)       // [2048, 2048]
#define SCRATCH_FLOATS (OFF_Y + ML_*DI_)

__device__ float g_scratch[SCRATCH_FLOATS];

// ---------------- helpers ----------------
__device__ __forceinline__ float softplusf(float v) {
    return (v > 20.f) ? v : log1pf(__expf(v));
}
__device__ __forceinline__ float siluf(float v) {
    return v / (1.f + __expf(-v));
}

// ---------------- embedding gather ----------------
__global__ void embed_kernel(const int* __restrict__ ids,
                             const float* __restrict__ emb,
                             float* __restrict__ out)
{
    int row = blockIdx.x;                 // b*L + l
    int id  = ids[row];
    const float4* src = (const float4*)(emb + (size_t)id * D_);
    float4* dst = (float4*)(out + (size_t)row * D_);
    for (int i = threadIdx.x; i < D_/4; i += blockDim.x) dst[i] = src[i];
}

// ---------------- residual accumulate + rmsnorm ----------------
// residual = first ? hidden : residual + hidden ; out = rmsnorm(residual)*w
__global__ void resid_rmsnorm(const float* __restrict__ hidden,
                              float* __restrict__ residual,
                              const float* __restrict__ w,
                              float* __restrict__ out,
                              int first)
{
    int row = blockIdx.x;                 // 2048 rows, 256 threads, D=1024 -> 1 float4/thread
    int t = threadIdx.x;
    const float4* h4 = (const float4*)(hidden + (size_t)row * D_);
    float4* r4 = (float4*)(residual + (size_t)row * D_);
    float4* o4 = (float4*)(out + (size_t)row * D_);
    const float4* w4 = (const float4*)w;

    float4 hv = h4[t];
    float4 rv;
    if (first) {
        rv = hv;
    } else {
        rv = r4[t];
        rv.x += hv.x; rv.y += hv.y; rv.z += hv.z; rv.w += hv.w;
    }
    r4[t] = rv;

    float s = rv.x*rv.x + rv.y*rv.y + rv.z*rv.z + rv.w*rv.w;
    // block reduce over 256 threads
    #pragma unroll
    for (int off = 16; off > 0; off >>= 1)
        s += __shfl_xor_sync(0xffffffffu, s, off);
    __shared__ float red[8];
    int warp = t >> 5, lane = t & 31;
    if (lane == 0) red[warp] = s;
    __syncthreads();
    float tot = red[0]+red[1]+red[2]+red[3]+red[4]+red[5]+red[6]+red[7];
    float scale = rsqrtf(tot / (float)D_ + EPS_);

    float4 wv = w4[t];
    float4 ov;
    ov.x = rv.x * scale * wv.x;
    ov.y = rv.y * scale * wv.y;
    ov.z = rv.z * scale * wv.z;
    ov.w = rv.w * scale * wv.w;
    o4[t] = ov;
}

// ---------------- causal depthwise conv (DC=4) + bias + silu ----------------
// x lives in first DI columns of xz [ML, 2*DI]; output xc [ML, DI]
__global__ void conv_silu(const float* __restrict__ xz,
                          const float* __restrict__ cw,
                          const float* __restrict__ cb,
                          float* __restrict__ xc)
{
    int idx = blockIdx.x * blockDim.x + threadIdx.x;   // over B*L*DI
    if (idx >= ML_ * DI_) return;
    int d  = idx % DI_;
    int bl = idx / DI_;
    int l  = bl % L_;
    int b  = bl / L_;

    float acc = cb[d];
    #pragma unroll
    for (int j = 0; j < DC_; j++) {
        int ls = l + j - (DC_ - 1);
        if (ls >= 0)
            acc += xz[((size_t)b * L_ + ls) * (2*DI_) + d] * cw[d * DC_ + j];
    }
    xc[idx] = siluf(acc);
}

// ---------------- selective scan (fused D-skip + z-gate) ----------------
// one thread per (b, d, s); 16 s-lanes per channel; 16 channels per block
__global__ void scan_kernel(const float* __restrict__ dt,
                            const float* __restrict__ xc,
                            const float* __restrict__ dbl,
                            const float* __restrict__ xz,
                            const float* __restrict__ alog,
                            const float* __restrict__ dsk,
                            float* __restrict__ y)
{
    int b    = blockIdx.x >> 7;             // DI/16 = 128 groups per batch
    int dgrp = blockIdx.x & 127;
    int s    = threadIdx.x & 15;
    int grp  = threadIdx.x >> 4;
    int d    = dgrp * 16 + grp;

    float a    = -__expf(alog[d * DS_ + s]);
    float dval = dsk[d];
    float h = 0.f;

    size_t base_bl = (size_t)b * L_;
    #pragma unroll 4
    for (int l = 0; l < L_; l++) {
        size_t bl = base_bl + l;
        float dtv = dt[bl * DI_ + d];
        float xv  = xc[bl * DI_ + d];
        float Bv  = dbl[bl * 96 + 64 + s];
        float Cv  = dbl[bl * 96 + 80 + s];

        float dA = __expf(dtv * a);
        h = fmaf(dA, h, dtv * Bv * xv);

        float p = h * Cv;
        p += __shfl_xor_sync(0xffffffffu, p, 8);
        p += __shfl_xor_sync(0xffffffffu, p, 4);
        p += __shfl_xor_sync(0xffffffffu, p, 2);
        p += __shfl_xor_sync(0xffffffffu, p, 1);

        if (s == 0) {
            float zv = xz[bl * (2*DI_) + DI_ + d];
            float yv = p + xv * dval;
            y[bl * DI_ + d] = yv * siluf(zv);
        }
    }
}

// ---------------- generic fp32 NT GEMM: C[M,N] = A[M,K] * W[N,K]^T ----------------
// BM=BN=128, BK=16, 256 threads, 8x8 per thread. M must be multiple of 128 (always 2048).
#define BM 128
#define BN 128
#define BK 16
#define TM 8
#define TN 8

template<int EPI>
__global__ __launch_bounds__(256)
void gemm_nt(const float* __restrict__ A, int lda,
             const float* __restrict__ W, int ldw,
             float* __restrict__ C, int ldc,
             const float* __restrict__ bias,
             int N, int K)
{
    __shared__ float sA[BK][BM + 4];
    __shared__ float sW[BK][BN + 4];

    const int tid = threadIdx.x;
    const int bm = blockIdx.y * BM;
    const int bn = blockIdx.x * BN;
    const int tx = tid & 15;
    const int ty = tid >> 4;

    float acc[TM][TN];
    #pragma unroll
    for (int i = 0; i < TM; i++)
        #pragma unroll
        for (int j = 0; j < TN; j++) acc[i][j] = 0.f;

    for (int k0 = 0; k0 < K; k0 += BK) {
        // load A tile: 128 rows x 16 cols = 512 float4
        #pragma unroll
        for (int t = 0; t < 2; t++) {
            int v = tid + t * 256;
            int row = v >> 2;
            int kv  = (v & 3) * 4;
            float4 f = *(const float4*)&A[(size_t)(bm + row) * lda + k0 + kv];
            sA[kv+0][row] = f.x; sA[kv+1][row] = f.y;
            sA[kv+2][row] = f.z; sA[kv+3][row] = f.w;
        }
        // load W tile (N-bounded)
        #pragma unroll
        for (int t = 0; t < 2; t++) {
            int v = tid + t * 256;
            int row = v >> 2;
            int kv  = (v & 3) * 4;
            int n = bn + row;
            float4 f = make_float4(0.f, 0.f, 0.f, 0.f);
            if (n < N) f = *(const float4*)&W[(size_t)n * ldw + k0 + kv];
            sW[kv+0][row] = f.x; sW[kv+1][row] = f.y;
            sW[kv+2][row] = f.z; sW[kv+3][row] = f.w;
        }
        __syncthreads();

        #pragma unroll
        for (int kk = 0; kk < BK; kk++) {
            float a[TM], b[TN];
            *(float4*)&a[0] = *(const float4*)&sA[kk][ty * TM];
            *(float4*)&a[4] = *(const float4*)&sA[kk][ty * TM + 4];
            *(float4*)&b[0] = *(const float4*)&sW[kk][tx * TN];
            *(float4*)&b[4] = *(const float4*)&sW[kk][tx * TN + 4];
            #pragma unroll
            for (int i = 0; i < TM; i++)
                #pragma unroll
                for (int j = 0; j < TN; j++)
                    acc[i][j] = fmaf(a[i], b[j], acc[i][j]);
        }
        __syncthreads();
    }

    #pragma unroll
    for (int i = 0; i < TM; i++) {
        int m = bm + ty * TM + i;
        #pragma unroll
        for (int j = 0; j < TN; j++) {
            int n = bn + tx * TN + j;
            if (n < N) {
                float v = acc[i][j];
                if (EPI == 1) { v = softplusf(v + bias[n]); }
                C[(size_t)m * ldc + n] = v;
            }
        }
    }
}

// ---------------- launch ----------------
extern "C" void kernel_launch(void* const* d_in, const int* in_sizes, int n_in,
                              void* d_out, int out_size)
{
    const int*   ids    = (const int*)  d_in[0];
    const float* emb    = (const float*)d_in[1];
    const float* norm_w = (const float*)d_in[2];
    const float* in_w   = (const float*)d_in[3];
    const float* cw     = (const float*)d_in[4];
    const float* cb     = (const float*)d_in[5];
    const float* xpw    = (const float*)d_in[6];
    const float* dtw    = (const float*)d_in[7];
    const float* dtb    = (const float*)d_in[8];
    const float* alog   = (const float*)d_in[9];
    const float* dsk    = (const float*)d_in[10];
    const float* ow     = (const float*)d_in[11];
    const float* nfw    = (const float*)d_in[12];
    float* logits = (float*)d_out;

    float* base = nullptr;
    cudaGetSymbolAddress((void**)&base, g_scratch);
    float* hidden = base + OFF_HIDDEN;
    float* resid  = base + OFF_RESID;
    float* hnorm  = base + OFF_HNORM;
    float* xz     = base + OFF_XZ;
    float* xconv  = base + OFF_XCONV;
    float* dbl    = base + OFF_DBL;
    float* dtbuf  = base + OFF_DT;
    float* ybuf   = base + OFF_Y;

    embed_kernel<<<ML_, 256>>>(ids, emb, hidden);

    for (int i = 0; i < NL_; i++) {
        resid_rmsnorm<<<ML_, 256>>>(hidden, resid, norm_w + (size_t)i * D_, hnorm, (i == 0) ? 1 : 0);

        // xz = hnorm @ in_w^T   [2048,4096]
        gemm_nt<0><<<dim3(2*DI_/BN, ML_/BM), 256>>>(
            hnorm, D_, in_w + (size_t)i * 2*DI_*D_, D_, xz, 2*DI_, nullptr, 2*DI_, D_);

        conv_silu<<<(ML_*DI_ + 255)/256, 256>>>(xz, cw + (size_t)i * DI_*DC_, cb + (size_t)i * DI_, xconv);

        // dbl = xconv @ xpw^T   [2048,96]
        gemm_nt<0><<<dim3(1, ML_/BM), 256>>>(
            xconv, DI_, xpw + (size_t)i * 96*DI_, DI_, dbl, 96, nullptr, 96, DI_);

        // dt = softplus(dbl[:, :64] @ dtw^T + dtb)   [2048,2048]
        gemm_nt<1><<<dim3(DI_/BN, ML_/BM), 256>>>(
            dbl, 96, dtw + (size_t)i * DI_*DTR_, DTR_, dtbuf, DI_, dtb + (size_t)i * DI_, DI_, DTR_);

        // selective scan + D-skip + z-gate -> ybuf
        scan_kernel<<<B_ * (DI_/16), 256>>>(
            dtbuf, xconv, dbl, xz, alog + (size_t)i * DI_*DS_, dsk + (size_t)i * DI_, ybuf);

        // hidden = ybuf @ ow^T   [2048,1024]
        gemm_nt<0><<<dim3(D_/BN, ML_/BM), 256>>>(
            ybuf, DI_, ow + (size_t)i * D_*DI_, DI_, hidden, D_, nullptr, D_, DI_);
    }

    resid_rmsnorm<<<ML_, 256>>>(hidden, resid, nfw, hnorm, 0);

    // logits = hnorm @ emb^T   [2048, 50280]
    gemm_nt<0><<<dim3((V_ + BN - 1)/BN, ML_/BM), 256>>>(
        hnorm, D_, emb, D_, logits, V_, nullptr, V_, D_);
}